// round 17
// baseline (speedup 1.0000x reference)
#include <cuda_runtime.h>
#include <cstddef>

#define NX 512
#define NU 32
#define NY 8
#define BB 64
#define TT 512
#define NSTEP 511
#define NPHASE 1022
#define NCTA 128
#define ROWP 516        // padded smem row (floats)
#define PREP_CTAS 128
#define NGRP 16         // 16 batch-groups of 4 batches; each CTA serves 2 chains

// ---------------- device scratch (sanctioned: __device__ globals) ----------------
__device__ float g_bufA[2 * NX * NX];
__device__ float g_bufB[2 * NX * NX];
__device__ float g_T[2 * NX * NX];
__device__ float g_W0[NX * NX];
__device__ float g_W1[NX * NX];
__device__ float g_Cp[NX * NY];
__device__ float g_inj[(size_t)NSTEP * 2 * BB * NX];   // [t][layer][b][n]
__device__ float g_s0 [(size_t)NSTEP * BB * NX];       // [t][b][n]
__device__ float g_s1 [BB * NX];                       // layer-1 state ping buffer
__device__ int   g_sync[64];                           // [0] = prep barrier counter
// per-(group,fs) phase flags, 16 ints (64B) apart: flag[(g*16+fs)*16], g<16
__device__ int   g_flags[256 * 16];

// ---------------- reset: zero s1 + all sync state ---------------------------------
__global__ void reset_kernel() {
    int idx = blockIdx.x * 256 + threadIdx.x;    // 128*256 = 32768
    g_s1[idx] = 0.0f;
    if (idx < 64) g_sync[idx] = 0;
    if (idx < 256 * 16) g_flags[idx] = 0;
}

// ---------------- prep grid barrier (proven atomic+volatile style) ----------------
__device__ __forceinline__ void gbar(int ph) {
    __syncthreads();
    if (threadIdx.x == 0) {
        __threadfence();
        atomicAdd(&g_sync[0], 1);
        volatile int* cnt = (volatile int*)&g_sync[0];
        while (*cnt < (ph + 1) * PREP_CTAS) { }
        __threadfence();
    }
    __syncthreads();
}

// one 32x32 output tile of a 512^3 GEMM.
// mode 0: C = A@B ; mode 1: C = 2*A - A@B ; mode 2: C = A@B^T
__device__ __forceinline__ void tile_mm(const float* __restrict__ A,
                                        const float* __restrict__ B,
                                        float* __restrict__ C,
                                        int row0, int col0, int mode,
                                        float (*As)[33], float (*Bs)[33]) {
    const int tid = threadIdx.x;
    const int tx = tid & 15, ty = tid >> 4;
    const int lm = tid >> 3;
    const int lk = (tid & 7) * 4;
    float c00 = 0.f, c01 = 0.f, c10 = 0.f, c11 = 0.f;
    for (int k0 = 0; k0 < 512; k0 += 32) {
        float4 a = *(const float4*)&A[(row0 + lm) * 512 + k0 + lk];
        As[lm][lk] = a.x; As[lm][lk+1] = a.y; As[lm][lk+2] = a.z; As[lm][lk+3] = a.w;
        if (mode == 2) {
            float4 b = *(const float4*)&B[(col0 + lm) * 512 + k0 + lk];
            Bs[lk  ][lm] = b.x; Bs[lk+1][lm] = b.y; Bs[lk+2][lm] = b.z; Bs[lk+3][lm] = b.w;
        } else {
            float4 b = *(const float4*)&B[(k0 + lm) * 512 + col0 + lk];
            Bs[lm][lk] = b.x; Bs[lm][lk+1] = b.y; Bs[lm][lk+2] = b.z; Bs[lm][lk+3] = b.w;
        }
        __syncthreads();
#pragma unroll
        for (int kk = 0; kk < 32; ++kk) {
            float a0 = As[ty*2][kk], a1 = As[ty*2+1][kk];
            float b0 = Bs[kk][tx*2], b1 = Bs[kk][tx*2+1];
            c00 = fmaf(a0, b0, c00); c01 = fmaf(a0, b1, c01);
            c10 = fmaf(a1, b0, c10); c11 = fmaf(a1, b1, c11);
        }
        __syncthreads();
    }
    if (mode == 1) {
        c00 = 2.f * A[(row0+ty*2  )*512 + col0+tx*2  ] - c00;
        c01 = 2.f * A[(row0+ty*2  )*512 + col0+tx*2+1] - c01;
        c10 = 2.f * A[(row0+ty*2+1)*512 + col0+tx*2  ] - c10;
        c11 = 2.f * A[(row0+ty*2+1)*512 + col0+tx*2+1] - c11;
    }
    C[(row0+ty*2  )*512 + col0+tx*2  ] = c00;
    C[(row0+ty*2  )*512 + col0+tx*2+1] = c01;
    C[(row0+ty*2+1)*512 + col0+tx*2  ] = c10;
    C[(row0+ty*2+1)*512 + col0+tx*2+1] = c11;
}

// ============== fused prep: Newton-Schulz inverse + W0/W1 + Cp ====================
__global__ void __launch_bounds__(256) prep_kernel(const float* __restrict__ E,
                                                   const float* __restrict__ Hw,
                                                   const float* __restrict__ Cw) {
    __shared__ float As[32][33];
    __shared__ float Bs[32][33];
    const int bid = blockIdx.x, tid = threadIdx.x;

    // phase 0: X0 = 2I - E (both layers)
    {
        int base = (bid * 256 + tid) * 16;
#pragma unroll
        for (int j = 0; j < 16; ++j) {
            int i = base + j;
            int r = (i >> 9) & 511, c = i & 511;
            g_bufA[i] = (r == c ? 2.0f : 0.0f) - E[i];
        }
    }
    gbar(0);

    float* X  = g_bufA;
    float* Xn = g_bufB;
    int ph = 1;
    for (int it = 0; it < 3; ++it) {
        for (int s = 0; s < 4; ++s) {                    // T = E @ X
            int task = bid + s * PREP_CTAS;              // 0..511
            int layer = task >> 8, tr = (task >> 4) & 15, tc = task & 15;
            int off = layer * 262144;
            tile_mm(E + off, X + off, g_T + off, tr * 32, tc * 32, 0, As, Bs);
        }
        gbar(ph++);
        for (int s = 0; s < 4; ++s) {                    // X' = 2X - X@T
            int task = bid + s * PREP_CTAS;
            int layer = task >> 8, tr = (task >> 4) & 15, tc = task & 15;
            int off = layer * 262144;
            tile_mm(X + off, g_T + off, Xn + off, tr * 32, tc * 32, 1, As, Bs);
        }
        gbar(ph++);
        float* sw = X; X = Xn; Xn = sw;
    }
    // final phase: W_l = Einv_l @ Hw_l^T ; Cp = Einv1 @ Cw^T
    for (int s = 0; s < 4; ++s) {
        int task = bid + s * PREP_CTAS;
        int layer = task >> 8, tr = (task >> 4) & 15, tc = task & 15;
        int off = layer * 262144;
        tile_mm(X + off, Hw + off, layer ? g_W1 : g_W0, tr * 32, tc * 32, 2, As, Bs);
    }
    if (bid < 16) {
        const float* Einv1 = X + 262144;
        int m = bid * 32 + (tid >> 3), j = tid & 7;
        float acc = 0.f;
        for (int k = 0; k < 512; ++k)
            acc = fmaf(Einv1[m * 512 + k], Cw[j * 512 + k], acc);
        g_Cp[m * 8 + j] = acc;
    }
}

// ---------------- inj[t][l][b][n] = Hb[l][n] + sum_k u[b][k][t]*Kw[l][n][k] -------
__global__ void __launch_bounds__(256) inj_kernel(const float* __restrict__ u,
                                                  const float* __restrict__ Kw,
                                                  const float* __restrict__ Hb) {
    __shared__ float us[64 * 33];
    __shared__ float kw[64 * 33];
    const int t = blockIdx.x;
    const int l = blockIdx.y >> 3, nb = blockIdx.y & 7;
    const int tid = threadIdx.x;
    for (int i = tid; i < 2048; i += 256) {
        int r = i >> 5, k = i & 31;
        us[r*33 + k] = u[r*16384 + k*512 + t];               // u[b][k][t]
        kw[r*33 + k] = Kw[l*16384 + nb*2048 + i];            // Kw[l][nb*64+r][k]
    }
    __syncthreads();
    const int b = tid >> 2, nq = tid & 3;
    for (int nn = 0; nn < 16; ++nn) {
        int nl = nq * 16 + nn;
        float acc = Hb[l*512 + nb*64 + nl];
#pragma unroll
        for (int k = 0; k < 32; ++k) acc = fmaf(us[b*33+k], kw[nl*33+k], acc);
        g_inj[(((size_t)t*2 + l)*64 + b)*512 + nb*64 + nl] = acc;
    }
}

// ---------------- main persistent recurrence kernel -------------------------------
// 128 CTAs = 8 q-slots x 16 feature-slices; each CTA serves 2 independent chains
// (batch-groups q and q+8, 4 batches each) with the SAME register-resident weight
// slice, alternating visits so one chain's inter-CTA sync latency hides under the
// other chain's compute. Warp 14 pre-polls the next visit's flags during finalize;
// spin fallback keeps correctness (monotonic flags -> deadlock-free).

#define KSLICE4(WP)                                                                 \
    _Pragma("unroll")                                                               \
    for (int cc = 0; cc < 8; ++cc) {                                                \
        _Pragma("unroll")                                                           \
        for (int b = 0; b < 4; ++b) {                                               \
            ulonglong2 sv = *(const ulonglong2*)(ss + b*ROWP + k0 + cc*4);          \
            asm("fma.rn.f32x2 %0, %1, %2, %0;" : "+l"(acc[b]) : "l"(sv.x), "l"(WP[2*cc]));   \
            asm("fma.rn.f32x2 %0, %1, %2, %0;" : "+l"(acc[b]) : "l"(sv.y), "l"(WP[2*cc+1])); \
        }                                                                           \
    }

__global__ void __launch_bounds__(512, 1) main_kernel() {
    __shared__ float ss[4 * ROWP];        // staged 4 batch rows (8.3 KB)
    __shared__ float red[16 * 128];       // partials [kw][b*32+f] (8 KB)
    __shared__ int s_ready;
    const int tid = threadIdx.x;
    const int q = blockIdx.x >> 4, fs = blockIdx.x & 15;
    const int nbase = fs * 32;
    const int kw = tid >> 5, lane = tid & 31;
    const int k0 = kw * 32;

    // ---- load both layers' weight column pairs into registers (once) ----
    unsigned long long wp0[16], wp1[16];
    {
        const int n = nbase + lane;
#pragma unroll
        for (int j = 0; j < 16; ++j) {
            float a0 = g_W0[(k0 + 2*j    )*512 + n];
            float a1 = g_W0[(k0 + 2*j + 1)*512 + n];
            float b0 = g_W1[(k0 + 2*j    )*512 + n];
            float b1 = g_W1[(k0 + 2*j + 1)*512 + n];
            asm("mov.b64 %0, {%1, %2};" : "=l"(wp0[j]) : "f"(a0), "f"(a1));
            asm("mov.b64 %0, {%1, %2};" : "=l"(wp1[j]) : "f"(b0), "f"(b1));
        }
    }
    if (tid == 0) s_ready = 0;
    __syncthreads();

    for (int p = 0; p < NPHASE; ++p) {
#pragma unroll 1
        for (int c = 0; c < 2; ++c) {
            const int g = q + 8 * c;          // chain (batch-group) id, 0..15
            const int bbase = g * 4;
            const int t = p >> 1, layer = p & 1;
            // inj load hoisted (precomputed; independent of flags)
            float injv = 0.0f;
            if (tid < 128)
                injv = __ldg(&g_inj[(((size_t)t*2 + layer)*64 + bbase + (tid >> 5))*512
                                    + nbase + (tid & 31)]);
            // A: wait (fast path: pre-polled readiness from previous visit)
            if (tid < 32) {
                if (!s_ready) {
                    volatile int* pf = (volatile int*)&g_flags[(g*16 + (lane & 15)) * 16];
                    for (;;) {
                        int ok = (*pf >= p);
                        if (__all_sync(0xffffffffu, ok)) break;
                    }
                }
                __threadfence();     // L1 invalidate: staging sees fresh L2 data
            }
            __syncthreads();
            // B: stage s_in[4][512] -> smem (one float4 per thread)
            {
                const float* sin = layer ? (g_s0 + (size_t)t * 32768) : g_s1;
                int bb = tid >> 7, k4 = (tid & 127) << 2;
                *(float4*)(ss + bb*ROWP + k4) = *(const float4*)(sin + (bbase+bb)*512 + k4);
            }
            __syncthreads();
            // C: per-warp k-slice partial GEMV (weights in regs), 4 batches
            unsigned long long acc[4];
#pragma unroll
            for (int b = 0; b < 4; ++b) acc[b] = 0ull;
            if (layer == 0) { KSLICE4(wp0) } else { KSLICE4(wp1) }
#pragma unroll
            for (int b = 0; b < 4; ++b) {
                float lo, hi;
                asm("mov.b64 {%0, %1}, %2;" : "=f"(lo), "=f"(hi) : "l"(acc[b]));
                red[kw*128 + b*32 + lane] = lo + hi;
            }
            __syncthreads();
            // D: finalize (threads 0..127) + pre-poll next visit (warp 14, idle here)
            if (tid < 128) {
                float sum = injv;
#pragma unroll
                for (int w = 0; w < 16; ++w) sum += red[w*128 + tid];
                float val = fmaxf(sum, 0.0f);
                float* dst = layer ? g_s1 : (g_s0 + (size_t)t * 32768);
                dst[(bbase + (tid >> 5))*512 + nbase + (tid & 31)] = val;
            }
            if (tid >= 448 && tid < 480) {     // warp 14: pre-poll next visit's flags
                int np = p + c;                // next visit: c==0 -> (q+8, p); c==1 -> (q, p+1)
                int gg = q + 8 * (c ^ 1);
                volatile int* pf = (volatile int*)&g_flags[(gg*16 + (lane & 15)) * 16];
                int ok = (*pf >= np);
                ok = __all_sync(0xffffffffu, ok);
                if (lane == 0) s_ready = ok;
            }
            __syncthreads();                   // outputs stored, s_ready published
            if (tid == 0) {
                __threadfence();
                *(volatile int*)&g_flags[(g*16 + fs) * 16] = p + 1;   // release
            }
        }
    }
}

// ---------------- output: y[b][j][t] = s0[t][b][:] @ Cp[:,j] + Cb[j] --------------
__global__ void __launch_bounds__(256) out_kernel(const float* __restrict__ Cb,
                                                  float* __restrict__ y) {
    __shared__ float cp[4096];
    const int t = blockIdx.x, tid = threadIdx.x;
    for (int i = tid; i < 4096; i += 256) cp[i] = g_Cp[i];
    __syncthreads();
    if (t == NSTEP) {   // t == 511: sel row is zero -> y = Cb
        for (int i = tid; i < 512; i += 256)
            y[(i >> 3) * 4096 + (i & 7) * 512 + NSTEP] = Cb[i & 7];
        return;
    }
    const int b = tid >> 2, jp = (tid & 3) * 2;
    const float* srw = g_s0 + (size_t)t * 32768 + b * 512;
    float a0 = Cb[jp], a1 = Cb[jp + 1];
    for (int k = 0; k < 512; k += 4) {
        float4 s = *(const float4*)(srw + k);
        a0 += s.x*cp[k*8+jp]     + s.y*cp[(k+1)*8+jp]     + s.z*cp[(k+2)*8+jp]     + s.w*cp[(k+3)*8+jp];
        a1 += s.x*cp[k*8+jp+1]   + s.y*cp[(k+1)*8+jp+1]   + s.z*cp[(k+2)*8+jp+1]   + s.w*cp[(k+3)*8+jp+1];
    }
    y[b*4096 + jp*512 + t]     = a0;
    y[b*4096 + (jp+1)*512 + t] = a1;
}

// ---------------- host orchestration ----------------------------------------------
extern "C" void kernel_launch(void* const* d_in, const int* in_sizes, int n_in,
                              void* d_out, int out_size) {
    (void)in_sizes; (void)n_in; (void)out_size;
    const float* u  = (const float*)d_in[0];
    const float* E  = (const float*)d_in[1];
    const float* Hw = (const float*)d_in[2];
    const float* Hb = (const float*)d_in[3];
    const float* Kw = (const float*)d_in[4];
    const float* Cw = (const float*)d_in[5];
    const float* Cb = (const float*)d_in[6];
    float* y = (float*)d_out;

    // launch 1: reset sync state + zero s1
    reset_kernel<<<128, 256>>>();
    // launch 2: fused precompute (Newton-Schulz inverse, W0/W1, Cp) @ 128 CTAs
    prep_kernel<<<PREP_CTAS, 256>>>(E, Hw, Cw);
    // launch 3: input injections
    inj_kernel<<<dim3(NSTEP, 16), 256>>>(u, Kw, Hb);
    // launch 4: persistent recurrence (ncu capture slot: 2 harness + 3 mine = skip 5)
    main_kernel<<<NCTA, 512>>>();
    // launch 5: output projection
    out_kernel<<<TT, 256>>>(Cb, y);
}